// round 3
// baseline (speedup 1.0000x reference)
#include <cuda_runtime.h>
#include <cuda_bf16.h>
#include <cstdint>

#define DIMC   768
#define NHEAD  12
#define HDIM   64
#define NBATCH 8
#define NTOK   1024
#define MTOK   (NBATCH * NTOK)

// Scratch (allocation-free)
__device__ float g_qkv[(size_t)MTOK * 3 * DIMC];
__device__ float g_attn[(size_t)MTOK * DIMC];

// ---------------------------------------------------------------------------
// helpers
// ---------------------------------------------------------------------------
__device__ __forceinline__ unsigned f2tf(float x) {
    unsigned r;
    asm("cvt.rna.tf32.f32 %0, %1;" : "=r"(r) : "f"(x));
    return r;
}

__device__ __forceinline__ void mma8(float* d, const unsigned* a, const unsigned* b) {
    asm volatile(
        "mma.sync.aligned.m16n8k8.row.col.f32.tf32.tf32.f32 "
        "{%0,%1,%2,%3},{%4,%5,%6,%7},{%8,%9},{%0,%1,%2,%3};\n"
        : "+f"(d[0]), "+f"(d[1]), "+f"(d[2]), "+f"(d[3])
        : "r"(a[0]), "r"(a[1]), "r"(a[2]), "r"(a[3]),
          "r"(b[0]), "r"(b[1]));
}

__device__ __forceinline__ void cp16(void* sdst, const void* gsrc) {
    unsigned sa = (unsigned)__cvta_generic_to_shared(sdst);
    asm volatile("cp.async.cg.shared.global [%0], [%1], 16;\n" :: "r"(sa), "l"(gsrc));
}
#define CP_COMMIT() asm volatile("cp.async.commit_group;\n" ::: "memory")
#define CP_WAIT0()  asm volatile("cp.async.wait_group 0;\n" ::: "memory")

// ---------------------------------------------------------------------------
// tf32 GEMM with cp.async 2-stage pipeline. 128x128x32 tile, 256 threads,
// warp tile 32x64. Raw fp32 staged to smem; cvt.rna.tf32 at fragment read.
// As stride 36, Bs stride 136 (conflict-free fragment LDS).
// ---------------------------------------------------------------------------
#define AS_ELT (128 * 36)
#define BS_ELT (32 * 136)
#define MM_SMEM ((2 * AS_ELT + 2 * BS_ELT) * 4)

template<bool BIAS>
__global__ void __launch_bounds__(256, 2) mm_tf32(
    const float* __restrict__ A, const float* __restrict__ B,
    const float* __restrict__ bias, float* __restrict__ C,
    int M, int N, int K)
{
    extern __shared__ float sm[];
    float* As = sm;                    // [2][128][36]
    float* Bs = sm + 2 * AS_ELT;       // [2][32][136]

    const int t    = threadIdx.x;
    const int lane = t & 31;
    const int warp = t >> 5;
    const int wm   = warp >> 1;
    const int wn   = warp & 1;
    const int g    = lane >> 2;
    const int tg   = lane & 3;
    const int bm   = blockIdx.y * 128;
    const int bn   = blockIdx.x * 128;

    float acc[2][8][4];
    #pragma unroll
    for (int mt = 0; mt < 2; mt++)
        #pragma unroll
        for (int nt = 0; nt < 8; nt++)
            #pragma unroll
            for (int i = 0; i < 4; i++) acc[mt][nt][i] = 0.f;

    auto prefetch = [&](int s, int k0) {
        float* as = As + s * AS_ELT;
        float* bs = Bs + s * BS_ELT;
        #pragma unroll
        for (int i = 0; i < 4; i++) {
            int v = t + 256 * i;
            int r = v >> 3, c = (v & 7) * 4;
            cp16(as + r * 36 + c, A + (size_t)(bm + r) * K + k0 + c);
        }
        #pragma unroll
        for (int i = 0; i < 4; i++) {
            int v = t + 256 * i;
            int r = v >> 5, c = (v & 31) * 4;
            cp16(bs + r * 136 + c, B + (size_t)(k0 + r) * N + bn + c);
        }
    };

    const int KT = K >> 5;
    prefetch(0, 0);
    CP_COMMIT();

    for (int kt = 0; kt < KT; kt++) {
        CP_WAIT0();
        __syncthreads();
        if (kt + 1 < KT) { prefetch((kt + 1) & 1, (kt + 1) * 32); CP_COMMIT(); }

        const float* as = As + (kt & 1) * AS_ELT;
        const float* bs = Bs + (kt & 1) * BS_ELT;

        #pragma unroll
        for (int ks = 0; ks < 4; ks++) {
            unsigned af[2][4], bf[8][2];
            #pragma unroll
            for (int mt = 0; mt < 2; mt++) {
                int r = wm * 32 + mt * 16 + g;
                int c = ks * 8 + tg;
                af[mt][0] = f2tf(as[r * 36 + c]);
                af[mt][1] = f2tf(as[(r + 8) * 36 + c]);
                af[mt][2] = f2tf(as[r * 36 + c + 4]);
                af[mt][3] = f2tf(as[(r + 8) * 36 + c + 4]);
            }
            #pragma unroll
            for (int nt = 0; nt < 8; nt++) {
                int cc = wn * 64 + nt * 8 + g;
                int r  = ks * 8 + tg;
                bf[nt][0] = f2tf(bs[r * 136 + cc]);
                bf[nt][1] = f2tf(bs[(r + 4) * 136 + cc]);
            }
            #pragma unroll
            for (int mt = 0; mt < 2; mt++)
                #pragma unroll
                for (int nt = 0; nt < 8; nt++)
                    mma8(acc[mt][nt], af[mt], bf[nt]);
        }
        __syncthreads();
    }

    #pragma unroll
    for (int mt = 0; mt < 2; mt++) {
        int r0 = bm + wm * 32 + mt * 16 + g;
        #pragma unroll
        for (int nt = 0; nt < 8; nt++) {
            int cc = bn + wn * 64 + nt * 8 + tg * 2;
            float2 v0 = make_float2(acc[mt][nt][0], acc[mt][nt][1]);
            float2 v1 = make_float2(acc[mt][nt][2], acc[mt][nt][3]);
            if (BIAS) {
                float2 bb = *(const float2*)(bias + cc);
                v0.x += bb.x; v0.y += bb.y;
                v1.x += bb.x; v1.y += bb.y;
            }
            *(float2*)(C + (size_t)r0 * N + cc)       = v0;
            *(float2*)(C + (size_t)(r0 + 8) * N + cc) = v1;
        }
    }
}

// ---------------------------------------------------------------------------
// Flash attention, tf32 mma, cp.async 2-stage K/V pipeline. 128 threads,
// warp = 16 q-rows. Raw fp32 K/V in smem; cvt at fragment read.
// Ks stride 68, Vs stride 72 (conflict-free).
// ---------------------------------------------------------------------------
#define KS_ELT (64 * 68)
#define VS_ELT (64 * 72)
#define AT_SMEM ((2 * KS_ELT + 2 * VS_ELT) * 4)

__global__ void __launch_bounds__(128) attn_tf32(
    const float* __restrict__ qkv, float* __restrict__ out)
{
    extern __shared__ float sm[];
    float* Ksm = sm;                   // [2][64][68]
    float* Vsm = sm + 2 * KS_ELT;      // [2][64][72]

    const int t    = threadIdx.x;
    const int lane = t & 31;
    const int warp = t >> 5;
    const int g    = lane >> 2;
    const int tg   = lane & 3;
    const int qt   = blockIdx.x;
    const int bh   = blockIdx.y;
    const int b    = bh / NHEAD;
    const int h    = bh - b * NHEAD;
    const size_t rs = 3 * DIMC;

    const float* kvb = qkv + (size_t)(b * NTOK) * rs + DIMC + h * HDIM;

    auto prefetch_kv = [&](int s, int kt) {
        const float* kb = kvb + (size_t)(kt * 64) * rs;
        float* ks = Ksm + s * KS_ELT;
        float* vs = Vsm + s * VS_ELT;
        #pragma unroll
        for (int i = 0; i < 8; i++) {
            int v = t + 128 * i;
            int r = v >> 4, c = (v & 15) * 4;
            const float* rp = kb + (size_t)r * rs;
            cp16(ks + r * 68 + c, rp + c);
            cp16(vs + r * 72 + c, rp + DIMC + c);
        }
    };

    // overlap first K/V tile load with Q staging
    prefetch_kv(0, 0);
    CP_COMMIT();

    // stage scaled Q through Vsm buf1 region (free until prefetch(1) at iter 0)
    {
        float* qs = Vsm + VS_ELT;
        const float* qbase = qkv + (size_t)(b * NTOK + qt * 64) * rs + h * HDIM;
        #pragma unroll
        for (int i = 0; i < 8; i++) {
            int v = t + 128 * i;
            int r = v >> 4, c = (v & 15) * 4;
            float4 q4 = *(const float4*)(qbase + (size_t)r * rs + c);
            q4.x *= 0.125f; q4.y *= 0.125f; q4.z *= 0.125f; q4.w *= 0.125f;
            *(float4*)(qs + r * 72 + c) = q4;
        }
    }
    __syncthreads();

    unsigned qa[8][4];
    {
        const float* qs = Vsm + VS_ELT;
        int r = warp * 16 + g;
        #pragma unroll
        for (int ks = 0; ks < 8; ks++) {
            int c = ks * 8 + tg;
            qa[ks][0] = f2tf(qs[r * 72 + c]);
            qa[ks][1] = f2tf(qs[(r + 8) * 72 + c]);
            qa[ks][2] = f2tf(qs[r * 72 + c + 4]);
            qa[ks][3] = f2tf(qs[(r + 8) * 72 + c + 4]);
        }
    }

    float oacc[8][4];
    #pragma unroll
    for (int dt = 0; dt < 8; dt++)
        #pragma unroll
        for (int i = 0; i < 4; i++) oacc[dt][i] = 0.f;

    float m0 = -1e30f, m1 = -1e30f, l0 = 0.f, l1 = 0.f;

    for (int kt = 0; kt < 16; kt++) {
        CP_WAIT0();
        __syncthreads();   // tile kt ready; all warps done with prior reads (incl. qa)
        if (kt + 1 < 16) { prefetch_kv((kt + 1) & 1, kt + 1); CP_COMMIT(); }

        const float* ks = Ksm + (kt & 1) * KS_ELT;
        const float* vs = Vsm + (kt & 1) * VS_ELT;

        // ---- S = Q @ K^T ----
        float sacc[8][4];
        #pragma unroll
        for (int nt = 0; nt < 8; nt++)
            #pragma unroll
            for (int i = 0; i < 4; i++) sacc[nt][i] = 0.f;

        #pragma unroll
        for (int kk = 0; kk < 8; kk++) {
            int d = kk * 8 + tg;
            #pragma unroll
            for (int nt = 0; nt < 8; nt++) {
                unsigned bf[2];
                int key = nt * 8 + g;
                bf[0] = f2tf(ks[key * 68 + d]);
                bf[1] = f2tf(ks[key * 68 + d + 4]);
                mma8(sacc[nt], qa[kk], bf);
            }
        }

        // ---- online softmax ----
        float mx0 = -1e30f, mx1 = -1e30f;
        #pragma unroll
        for (int nt = 0; nt < 8; nt++) {
            mx0 = fmaxf(mx0, fmaxf(sacc[nt][0], sacc[nt][1]));
            mx1 = fmaxf(mx1, fmaxf(sacc[nt][2], sacc[nt][3]));
        }
        mx0 = fmaxf(mx0, __shfl_xor_sync(0xFFFFFFFFu, mx0, 1));
        mx0 = fmaxf(mx0, __shfl_xor_sync(0xFFFFFFFFu, mx0, 2));
        mx1 = fmaxf(mx1, __shfl_xor_sync(0xFFFFFFFFu, mx1, 1));
        mx1 = fmaxf(mx1, __shfl_xor_sync(0xFFFFFFFFu, mx1, 2));

        float nm0 = fmaxf(m0, mx0), nm1 = fmaxf(m1, mx1);
        float a0 = __expf(m0 - nm0), a1 = __expf(m1 - nm1);
        m0 = nm0; m1 = nm1;

        float s0 = 0.f, s1 = 0.f;
        unsigned pf[8][4];
        #pragma unroll
        for (int nt = 0; nt < 8; nt++) {
            float p0 = __expf(sacc[nt][0] - m0);
            float p1 = __expf(sacc[nt][1] - m0);
            float p2 = __expf(sacc[nt][2] - m1);
            float p3 = __expf(sacc[nt][3] - m1);
            s0 += p0 + p1;
            s1 += p2 + p3;
            pf[nt][0] = f2tf(p0); pf[nt][1] = f2tf(p1);
            pf[nt][2] = f2tf(p2); pf[nt][3] = f2tf(p3);
            oacc[nt][0] *= a0; oacc[nt][1] *= a0;
            oacc[nt][2] *= a1; oacc[nt][3] *= a1;
        }
        s0 += __shfl_xor_sync(0xFFFFFFFFu, s0, 1);
        s0 += __shfl_xor_sync(0xFFFFFFFFu, s0, 2);
        s1 += __shfl_xor_sync(0xFFFFFFFFu, s1, 1);
        s1 += __shfl_xor_sync(0xFFFFFFFFu, s1, 2);
        l0 = l0 * a0 + s0;
        l1 = l1 * a1 + s1;

        // ---- O += P @ V (P: C-layout -> A-layout via shuffles) ----
        const int src0 = (lane & ~3) | (tg >> 1);
        const int src2 = src0 + 2;
        #pragma unroll
        for (int kk = 0; kk < 8; kk++) {
            unsigned x0 = __shfl_sync(0xFFFFFFFFu, pf[kk][0], src0);
            unsigned x1 = __shfl_sync(0xFFFFFFFFu, pf[kk][1], src0);
            unsigned x2 = __shfl_sync(0xFFFFFFFFu, pf[kk][2], src0);
            unsigned x3 = __shfl_sync(0xFFFFFFFFu, pf[kk][3], src0);
            unsigned y0 = __shfl_sync(0xFFFFFFFFu, pf[kk][0], src2);
            unsigned y1 = __shfl_sync(0xFFFFFFFFu, pf[kk][1], src2);
            unsigned y2 = __shfl_sync(0xFFFFFFFFu, pf[kk][2], src2);
            unsigned y3 = __shfl_sync(0xFFFFFFFFu, pf[kk][3], src2);
            unsigned pa[4];
            pa[0] = (tg & 1) ? x1 : x0;
            pa[1] = (tg & 1) ? x3 : x2;
            pa[2] = (tg & 1) ? y1 : y0;
            pa[3] = (tg & 1) ? y3 : y2;

            int key = kk * 8 + tg;
            #pragma unroll
            for (int dt = 0; dt < 8; dt++) {
                unsigned vb[2];
                int d = dt * 8 + g;
                vb[0] = f2tf(vs[key * 72 + d]);
                vb[1] = f2tf(vs[(key + 4) * 72 + d]);
                mma8(oacc[dt], pa, vb);
            }
        }
    }

    // ---- epilogue ----
    float inv0 = 1.0f / l0, inv1 = 1.0f / l1;
    int token = b * NTOK + qt * 64 + warp * 16 + g;
    float* op = out + (size_t)token * DIMC + h * HDIM;
    #pragma unroll
    for (int dt = 0; dt < 8; dt++) {
        int d = dt * 8 + tg * 2;
        *(float2*)(op + d)            = make_float2(oacc[dt][0] * inv0, oacc[dt][1] * inv0);
        *(float2*)(op + 8 * DIMC + d) = make_float2(oacc[dt][2] * inv1, oacc[dt][3] * inv1);
    }
}

// ---------------------------------------------------------------------------
// kernel_launch
// ---------------------------------------------------------------------------
extern "C" void kernel_launch(void* const* d_in, const int* in_sizes, int n_in,
                              void* d_out, int out_size)
{
    const float* x      = (const float*)d_in[0];
    const float* w_qkv  = (const float*)d_in[1];
    const float* w_proj = (const float*)d_in[2];
    const float* b_proj = (const float*)d_in[3];
    float*       out    = (float*)d_out;

    void *qkv_p = nullptr, *attn_p = nullptr;
    cudaGetSymbolAddress(&qkv_p, g_qkv);
    cudaGetSymbolAddress(&attn_p, g_attn);

    static bool attr_set = false;
    if (!attr_set) {
        cudaFuncSetAttribute(mm_tf32<false>, cudaFuncAttributeMaxDynamicSharedMemorySize, MM_SMEM);
        cudaFuncSetAttribute(mm_tf32<true>,  cudaFuncAttributeMaxDynamicSharedMemorySize, MM_SMEM);
        cudaFuncSetAttribute(attn_tf32,      cudaFuncAttributeMaxDynamicSharedMemorySize, AT_SMEM);
        attr_set = true;
    }

    mm_tf32<false><<<dim3((3 * DIMC) / 128, MTOK / 128), 256, MM_SMEM>>>(
        x, w_qkv, nullptr, (float*)qkv_p, MTOK, 3 * DIMC, DIMC);

    attn_tf32<<<dim3(NTOK / 64, NBATCH * NHEAD), 128, AT_SMEM>>>(
        (const float*)qkv_p, (float*)attn_p);

    mm_tf32<true><<<dim3(DIMC / 128, MTOK / 128), 256, MM_SMEM>>>(
        (const float*)attn_p, w_proj, b_proj, out, MTOK, DIMC, DIMC);
}

// round 4
// speedup vs baseline: 1.2487x; 1.2487x over previous
#include <cuda_runtime.h>
#include <cuda_bf16.h>
#include <cstdint>

#define DIMC   768
#define NHEAD  12
#define HDIM   64
#define NBATCH 8
#define NTOK   1024
#define MTOK   (NBATCH * NTOK)

// Scratch (allocation-free)
__device__ float g_qkv[(size_t)MTOK * 3 * DIMC];   // tf32-rounded QKV
__device__ float g_attn[(size_t)MTOK * DIMC];      // tf32-rounded attn out
__device__ float g_x[(size_t)MTOK * DIMC];         // tf32-rounded x
__device__ float g_wqkv[(size_t)DIMC * 3 * DIMC];  // tf32-rounded w_qkv
__device__ float g_wproj[(size_t)DIMC * DIMC];     // tf32-rounded w_proj

// ---------------------------------------------------------------------------
// helpers
// ---------------------------------------------------------------------------
__device__ __forceinline__ unsigned f2tf(float x) {
    unsigned r;
    asm("cvt.rna.tf32.f32 %0, %1;" : "=r"(r) : "f"(x));
    return r;
}

__device__ __forceinline__ void mma8(float* d, const unsigned* a, const unsigned* b) {
    asm volatile(
        "mma.sync.aligned.m16n8k8.row.col.f32.tf32.tf32.f32 "
        "{%0,%1,%2,%3},{%4,%5,%6,%7},{%8,%9},{%0,%1,%2,%3};\n"
        : "+f"(d[0]), "+f"(d[1]), "+f"(d[2]), "+f"(d[3])
        : "r"(a[0]), "r"(a[1]), "r"(a[2]), "r"(a[3]),
          "r"(b[0]), "r"(b[1]));
}

__device__ __forceinline__ void cp16(void* sdst, const void* gsrc) {
    unsigned sa = (unsigned)__cvta_generic_to_shared(sdst);
    asm volatile("cp.async.cg.shared.global [%0], [%1], 16;\n" :: "r"(sa), "l"(gsrc));
}
#define CP_COMMIT() asm volatile("cp.async.commit_group;\n" ::: "memory")
#define CP_WAIT0()  asm volatile("cp.async.wait_group 0;\n" ::: "memory")

// ---------------------------------------------------------------------------
// Elementwise tf32 rounding pass: out[i] = tf32(in[i])
// ---------------------------------------------------------------------------
__global__ void __launch_bounds__(256) conv_tf32(
    const float4* __restrict__ in, float4* __restrict__ out, int n4)
{
    int i = blockIdx.x * 256 + threadIdx.x;
    if (i < n4) {
        float4 v = in[i];
        uint4 u;
        u.x = f2tf(v.x); u.y = f2tf(v.y); u.z = f2tf(v.z); u.w = f2tf(v.w);
        *(uint4*)&out[i] = u;
    }
}

// ---------------------------------------------------------------------------
// tf32 GEMM, cp.async 2-stage pipeline, NO cvt in hot loop (inputs pre-rounded).
// 128x128x32 tile, 256 threads, warp tile 32x64.
// CVTOUT: round outputs to tf32 (when output feeds another tf32 matmul).
// ---------------------------------------------------------------------------
#define AS_ELT (128 * 36)
#define BS_ELT (32 * 136)
#define MM_SMEM ((2 * AS_ELT + 2 * BS_ELT) * 4)

template<bool BIAS, bool CVTOUT>
__global__ void __launch_bounds__(256, 2) mm_tf32(
    const float* __restrict__ A, const float* __restrict__ B,
    const float* __restrict__ bias, float* __restrict__ C,
    int M, int N, int K)
{
    extern __shared__ float sm[];
    float* As = sm;
    float* Bs = sm + 2 * AS_ELT;

    const int t    = threadIdx.x;
    const int lane = t & 31;
    const int warp = t >> 5;
    const int wm   = warp >> 1;
    const int wn   = warp & 1;
    const int g    = lane >> 2;
    const int tg   = lane & 3;
    const int bm   = blockIdx.y * 128;
    const int bn   = blockIdx.x * 128;

    float acc[2][8][4];
    #pragma unroll
    for (int mt = 0; mt < 2; mt++)
        #pragma unroll
        for (int nt = 0; nt < 8; nt++)
            #pragma unroll
            for (int i = 0; i < 4; i++) acc[mt][nt][i] = 0.f;

    auto prefetch = [&](int s, int k0) {
        float* as = As + s * AS_ELT;
        float* bs = Bs + s * BS_ELT;
        #pragma unroll
        for (int i = 0; i < 4; i++) {
            int v = t + 256 * i;
            int r = v >> 3, c = (v & 7) * 4;
            cp16(as + r * 36 + c, A + (size_t)(bm + r) * K + k0 + c);
        }
        #pragma unroll
        for (int i = 0; i < 4; i++) {
            int v = t + 256 * i;
            int r = v >> 5, c = (v & 31) * 4;
            cp16(bs + r * 136 + c, B + (size_t)(k0 + r) * N + bn + c);
        }
    };

    const int KT = K >> 5;
    prefetch(0, 0);
    CP_COMMIT();

    for (int kt = 0; kt < KT; kt++) {
        CP_WAIT0();
        __syncthreads();
        if (kt + 1 < KT) { prefetch((kt + 1) & 1, (kt + 1) * 32); CP_COMMIT(); }

        const unsigned* as = (const unsigned*)(As + (kt & 1) * AS_ELT);
        const unsigned* bs = (const unsigned*)(Bs + (kt & 1) * BS_ELT);

        #pragma unroll
        for (int ks = 0; ks < 4; ks++) {
            unsigned af[2][4], bf[8][2];
            #pragma unroll
            for (int mt = 0; mt < 2; mt++) {
                int r = wm * 32 + mt * 16 + g;
                int c = ks * 8 + tg;
                af[mt][0] = as[r * 36 + c];
                af[mt][1] = as[(r + 8) * 36 + c];
                af[mt][2] = as[r * 36 + c + 4];
                af[mt][3] = as[(r + 8) * 36 + c + 4];
            }
            #pragma unroll
            for (int nt = 0; nt < 8; nt++) {
                int cc = wn * 64 + nt * 8 + g;
                int r  = ks * 8 + tg;
                bf[nt][0] = bs[r * 136 + cc];
                bf[nt][1] = bs[(r + 4) * 136 + cc];
            }
            #pragma unroll
            for (int mt = 0; mt < 2; mt++)
                #pragma unroll
                for (int nt = 0; nt < 8; nt++)
                    mma8(acc[mt][nt], af[mt], bf[nt]);
        }
        __syncthreads();
    }

    #pragma unroll
    for (int mt = 0; mt < 2; mt++) {
        int r0 = bm + wm * 32 + mt * 16 + g;
        #pragma unroll
        for (int nt = 0; nt < 8; nt++) {
            int cc = bn + wn * 64 + nt * 8 + tg * 2;
            float2 v0 = make_float2(acc[mt][nt][0], acc[mt][nt][1]);
            float2 v1 = make_float2(acc[mt][nt][2], acc[mt][nt][3]);
            if (BIAS) {
                float2 bb = *(const float2*)(bias + cc);
                v0.x += bb.x; v0.y += bb.y;
                v1.x += bb.x; v1.y += bb.y;
            }
            if (CVTOUT) {
                v0.x = __uint_as_float(f2tf(v0.x));
                v0.y = __uint_as_float(f2tf(v0.y));
                v1.x = __uint_as_float(f2tf(v1.x));
                v1.y = __uint_as_float(f2tf(v1.y));
            }
            *(float2*)(C + (size_t)r0 * N + cc)       = v0;
            *(float2*)(C + (size_t)(r0 + 8) * N + cc) = v1;
        }
    }
}

// ---------------------------------------------------------------------------
// Flash attention, tf32 mma, cp.async 2-stage K/V pipeline, NO K/V/Q cvts
// (qkv pre-rounded to tf32 by GEMM epilogue). Output rounded for proj GEMM.
// ---------------------------------------------------------------------------
#define KS_ELT (64 * 68)
#define VS_ELT (64 * 72)
#define AT_SMEM ((2 * KS_ELT + 2 * VS_ELT) * 4)

__global__ void __launch_bounds__(128) attn_tf32(
    const float* __restrict__ qkv, float* __restrict__ out)
{
    extern __shared__ float sm[];
    float* Ksm = sm;
    float* Vsm = sm + 2 * KS_ELT;

    const int t    = threadIdx.x;
    const int lane = t & 31;
    const int warp = t >> 5;
    const int g    = lane >> 2;
    const int tg   = lane & 3;
    const int qt   = blockIdx.x;
    const int bh   = blockIdx.y;
    const int b    = bh / NHEAD;
    const int h    = bh - b * NHEAD;
    const size_t rs = 3 * DIMC;

    const float* kvb = qkv + (size_t)(b * NTOK) * rs + DIMC + h * HDIM;

    auto prefetch_kv = [&](int s, int kt) {
        const float* kb = kvb + (size_t)(kt * 64) * rs;
        float* ks = Ksm + s * KS_ELT;
        float* vs = Vsm + s * VS_ELT;
        #pragma unroll
        for (int i = 0; i < 8; i++) {
            int v = t + 128 * i;
            int r = v >> 4, c = (v & 15) * 4;
            const float* rp = kb + (size_t)r * rs;
            cp16(ks + r * 68 + c, rp + c);
            cp16(vs + r * 72 + c, rp + DIMC + c);
        }
    };

    prefetch_kv(0, 0);
    CP_COMMIT();

    // stage scaled Q through Vsm buf1 (free until prefetch(1) after first sync)
    {
        float* qs = Vsm + VS_ELT;
        const float* qbase = qkv + (size_t)(b * NTOK + qt * 64) * rs + h * HDIM;
        #pragma unroll
        for (int i = 0; i < 8; i++) {
            int v = t + 128 * i;
            int r = v >> 4, c = (v & 15) * 4;
            float4 q4 = *(const float4*)(qbase + (size_t)r * rs + c);
            // values already tf32-rounded; *0.125f is exact (exponent shift)
            q4.x *= 0.125f; q4.y *= 0.125f; q4.z *= 0.125f; q4.w *= 0.125f;
            *(float4*)(qs + r * 72 + c) = q4;
        }
    }
    __syncthreads();

    unsigned qa[8][4];
    {
        const unsigned* qs = (const unsigned*)(Vsm + VS_ELT);
        int r = warp * 16 + g;
        #pragma unroll
        for (int ks = 0; ks < 8; ks++) {
            int c = ks * 8 + tg;
            qa[ks][0] = qs[r * 72 + c];
            qa[ks][1] = qs[(r + 8) * 72 + c];
            qa[ks][2] = qs[r * 72 + c + 4];
            qa[ks][3] = qs[(r + 8) * 72 + c + 4];
        }
    }

    float oacc[8][4];
    #pragma unroll
    for (int dt = 0; dt < 8; dt++)
        #pragma unroll
        for (int i = 0; i < 4; i++) oacc[dt][i] = 0.f;

    float m0 = -1e30f, m1 = -1e30f, l0 = 0.f, l1 = 0.f;

    for (int kt = 0; kt < 16; kt++) {
        CP_WAIT0();
        __syncthreads();
        if (kt + 1 < 16) { prefetch_kv((kt + 1) & 1, kt + 1); CP_COMMIT(); }

        const unsigned* ks = (const unsigned*)(Ksm + (kt & 1) * KS_ELT);
        const unsigned* vs = (const unsigned*)(Vsm + (kt & 1) * VS_ELT);

        // ---- S = Q @ K^T ----
        float sacc[8][4];
        #pragma unroll
        for (int nt = 0; nt < 8; nt++)
            #pragma unroll
            for (int i = 0; i < 4; i++) sacc[nt][i] = 0.f;

        #pragma unroll
        for (int kk = 0; kk < 8; kk++) {
            int d = kk * 8 + tg;
            #pragma unroll
            for (int nt = 0; nt < 8; nt++) {
                unsigned bf[2];
                int key = nt * 8 + g;
                bf[0] = ks[key * 68 + d];
                bf[1] = ks[key * 68 + d + 4];
                mma8(sacc[nt], qa[kk], bf);
            }
        }

        // ---- online softmax ----
        float mx0 = -1e30f, mx1 = -1e30f;
        #pragma unroll
        for (int nt = 0; nt < 8; nt++) {
            mx0 = fmaxf(mx0, fmaxf(sacc[nt][0], sacc[nt][1]));
            mx1 = fmaxf(mx1, fmaxf(sacc[nt][2], sacc[nt][3]));
        }
        mx0 = fmaxf(mx0, __shfl_xor_sync(0xFFFFFFFFu, mx0, 1));
        mx0 = fmaxf(mx0, __shfl_xor_sync(0xFFFFFFFFu, mx0, 2));
        mx1 = fmaxf(mx1, __shfl_xor_sync(0xFFFFFFFFu, mx1, 1));
        mx1 = fmaxf(mx1, __shfl_xor_sync(0xFFFFFFFFu, mx1, 2));

        float nm0 = fmaxf(m0, mx0), nm1 = fmaxf(m1, mx1);
        float a0 = __expf(m0 - nm0), a1 = __expf(m1 - nm1);
        m0 = nm0; m1 = nm1;

        float s0 = 0.f, s1 = 0.f;
        unsigned pf[8][4];
        #pragma unroll
        for (int nt = 0; nt < 8; nt++) {
            float p0 = __expf(sacc[nt][0] - m0);
            float p1 = __expf(sacc[nt][1] - m0);
            float p2 = __expf(sacc[nt][2] - m1);
            float p3 = __expf(sacc[nt][3] - m1);
            s0 += p0 + p1;
            s1 += p2 + p3;
            pf[nt][0] = f2tf(p0); pf[nt][1] = f2tf(p1);
            pf[nt][2] = f2tf(p2); pf[nt][3] = f2tf(p3);
            oacc[nt][0] *= a0; oacc[nt][1] *= a0;
            oacc[nt][2] *= a1; oacc[nt][3] *= a1;
        }
        s0 += __shfl_xor_sync(0xFFFFFFFFu, s0, 1);
        s0 += __shfl_xor_sync(0xFFFFFFFFu, s0, 2);
        s1 += __shfl_xor_sync(0xFFFFFFFFu, s1, 1);
        s1 += __shfl_xor_sync(0xFFFFFFFFu, s1, 2);
        l0 = l0 * a0 + s0;
        l1 = l1 * a1 + s1;

        // ---- O += P @ V ----
        const int src0 = (lane & ~3) | (tg >> 1);
        const int src2 = src0 + 2;
        #pragma unroll
        for (int kk = 0; kk < 8; kk++) {
            unsigned x0 = __shfl_sync(0xFFFFFFFFu, pf[kk][0], src0);
            unsigned x1 = __shfl_sync(0xFFFFFFFFu, pf[kk][1], src0);
            unsigned x2 = __shfl_sync(0xFFFFFFFFu, pf[kk][2], src0);
            unsigned x3 = __shfl_sync(0xFFFFFFFFu, pf[kk][3], src0);
            unsigned y0 = __shfl_sync(0xFFFFFFFFu, pf[kk][0], src2);
            unsigned y1 = __shfl_sync(0xFFFFFFFFu, pf[kk][1], src2);
            unsigned y2 = __shfl_sync(0xFFFFFFFFu, pf[kk][2], src2);
            unsigned y3 = __shfl_sync(0xFFFFFFFFu, pf[kk][3], src2);
            unsigned pa[4];
            pa[0] = (tg & 1) ? x1 : x0;
            pa[1] = (tg & 1) ? x3 : x2;
            pa[2] = (tg & 1) ? y1 : y0;
            pa[3] = (tg & 1) ? y3 : y2;

            int key = kk * 8 + tg;
            #pragma unroll
            for (int dt = 0; dt < 8; dt++) {
                unsigned vb[2];
                int d = dt * 8 + g;
                vb[0] = vs[key * 72 + d];
                vb[1] = vs[(key + 4) * 72 + d];
                mma8(oacc[dt], pa, vb);
            }
        }
    }

    // ---- epilogue: normalize, round to tf32 (feeds proj GEMM), store ----
    float inv0 = 1.0f / l0, inv1 = 1.0f / l1;
    int token = b * NTOK + qt * 64 + warp * 16 + g;
    float* op = out + (size_t)token * DIMC + h * HDIM;
    #pragma unroll
    for (int dt = 0; dt < 8; dt++) {
        int d = dt * 8 + tg * 2;
        float2 v0 = make_float2(__uint_as_float(f2tf(oacc[dt][0] * inv0)),
                                __uint_as_float(f2tf(oacc[dt][1] * inv0)));
        float2 v1 = make_float2(__uint_as_float(f2tf(oacc[dt][2] * inv1)),
                                __uint_as_float(f2tf(oacc[dt][3] * inv1)));
        *(float2*)(op + d)            = v0;
        *(float2*)(op + 8 * DIMC + d) = v1;
    }
}

// ---------------------------------------------------------------------------
// kernel_launch
// ---------------------------------------------------------------------------
extern "C" void kernel_launch(void* const* d_in, const int* in_sizes, int n_in,
                              void* d_out, int out_size)
{
    const float* x      = (const float*)d_in[0];
    const float* w_qkv  = (const float*)d_in[1];
    const float* w_proj = (const float*)d_in[2];
    const float* b_proj = (const float*)d_in[3];
    float*       out    = (float*)d_out;

    void *qkv_p, *attn_p, *x_p, *wqkv_p, *wproj_p;
    cudaGetSymbolAddress(&qkv_p,  g_qkv);
    cudaGetSymbolAddress(&attn_p, g_attn);
    cudaGetSymbolAddress(&x_p,    g_x);
    cudaGetSymbolAddress(&wqkv_p, g_wqkv);
    cudaGetSymbolAddress(&wproj_p,g_wproj);

    static bool attr_set = false;
    if (!attr_set) {
        cudaFuncSetAttribute((const void*)mm_tf32<false,true>,  cudaFuncAttributeMaxDynamicSharedMemorySize, MM_SMEM);
        cudaFuncSetAttribute((const void*)mm_tf32<true,false>,  cudaFuncAttributeMaxDynamicSharedMemorySize, MM_SMEM);
        cudaFuncSetAttribute((const void*)attn_tf32,            cudaFuncAttributeMaxDynamicSharedMemorySize, AT_SMEM);
        attr_set = true;
    }

    // 0) pre-round inputs to tf32
    {
        int n4x = MTOK * DIMC / 4;
        int n4q = DIMC * 3 * DIMC / 4;
        int n4p = DIMC * DIMC / 4;
        conv_tf32<<<(n4x + 255) / 256, 256>>>((const float4*)x,      (float4*)x_p,     n4x);
        conv_tf32<<<(n4q + 255) / 256, 256>>>((const float4*)w_qkv,  (float4*)wqkv_p,  n4q);
        conv_tf32<<<(n4p + 255) / 256, 256>>>((const float4*)w_proj, (float4*)wproj_p, n4p);
    }

    // 1) QKV GEMM (outputs tf32-rounded)
    mm_tf32<false, true><<<dim3((3 * DIMC) / 128, MTOK / 128), 256, MM_SMEM>>>(
        (const float*)x_p, (const float*)wqkv_p, nullptr, (float*)qkv_p,
        MTOK, 3 * DIMC, DIMC);

    // 2) Attention (outputs tf32-rounded)
    attn_tf32<<<dim3(NTOK / 64, NBATCH * NHEAD), 128, AT_SMEM>>>(
        (const float*)qkv_p, (float*)attn_p);

    // 3) Projection + bias (full fp32 output)
    mm_tf32<true, false><<<dim3(DIMC / 128, MTOK / 128), 256, MM_SMEM>>>(
        (const float*)attn_p, (const float*)wproj_p, b_proj, out,
        MTOK, DIMC, DIMC);
}

// round 6
// speedup vs baseline: 2.0031x; 1.6042x over previous
#include <cuda_runtime.h>
#include <cuda_fp16.h>
#include <cstdint>

#define DIMC   768
#define NHEAD  12
#define HDIM   64
#define NBATCH 8
#define NTOK   1024
#define MTOK   (NBATCH * NTOK)

// Scratch (allocation-free), all fp16
__device__ __half g_qkv[(size_t)MTOK * 3 * DIMC];    // QKV (half)
__device__ __half g_attn[(size_t)MTOK * DIMC];       // attn out (half)
__device__ __half g_x[(size_t)MTOK * DIMC];          // x (half)
__device__ __half g_wqkvT[(size_t)3 * DIMC * DIMC];  // w_qkv^T [2304][768]
__device__ __half g_wprojT[(size_t)DIMC * DIMC];     // w_proj^T [768][768]

// ---------------------------------------------------------------------------
// helpers
// ---------------------------------------------------------------------------
__device__ __forceinline__ unsigned pack2(float a, float b) {
    __half2 h = __floats2half2_rn(a, b);
    return *(unsigned*)&h;
}

// D += A @ B  (m16n8k16, fp16 inputs, f32 accumulate)
__device__ __forceinline__ void mma16(float* d, const unsigned* a, const unsigned* b) {
    asm volatile(
        "mma.sync.aligned.m16n8k16.row.col.f32.f16.f16.f32 "
        "{%0,%1,%2,%3},{%4,%5,%6,%7},{%8,%9},{%0,%1,%2,%3};\n"
        : "+f"(d[0]), "+f"(d[1]), "+f"(d[2]), "+f"(d[3])
        : "r"(a[0]), "r"(a[1]), "r"(a[2]), "r"(a[3]),
          "r"(b[0]), "r"(b[1]));
}

__device__ __forceinline__ void cp16(void* sdst, const void* gsrc) {
    unsigned sa = (unsigned)__cvta_generic_to_shared(sdst);
    asm volatile("cp.async.cg.shared.global [%0], [%1], 16;\n" :: "r"(sa), "l"(gsrc));
}
#define CP_COMMIT() asm volatile("cp.async.commit_group;\n" ::: "memory")
#define CP_WAIT0()  asm volatile("cp.async.wait_group 0;\n" ::: "memory")

__device__ __forceinline__ void ldmx4t(unsigned* r, unsigned saddr) {
    asm volatile(
        "ldmatrix.sync.aligned.m8n8.x4.trans.shared.b16 {%0,%1,%2,%3}, [%4];"
        : "=r"(r[0]), "=r"(r[1]), "=r"(r[2]), "=r"(r[3]) : "r"(saddr));
}

// ---------------------------------------------------------------------------
// prep: x -> half; weights [K][N] f32 -> [N][K] half (transposed)
// ---------------------------------------------------------------------------
__global__ void __launch_bounds__(256) conv_half(
    const float4* __restrict__ in, __half* __restrict__ out, int n4)
{
    int i = blockIdx.x * 256 + threadIdx.x;
    if (i < n4) {
        float4 v = in[i];
        uint2 u;
        u.x = pack2(v.x, v.y);
        u.y = pack2(v.z, v.w);
        *(uint2*)(out + 4 * (size_t)i) = u;
    }
}

__global__ void __launch_bounds__(256) transpose_half(
    const float* __restrict__ in, __half* __restrict__ out, int K, int N)
{
    __shared__ float tile[32][33];
    int bx = blockIdx.x * 32;   // N offset
    int by = blockIdx.y * 32;   // K offset
    int tx = threadIdx.x & 31, ty = threadIdx.x >> 5;
    #pragma unroll
    for (int j = 0; j < 32; j += 8)
        tile[ty + j][tx] = in[(size_t)(by + ty + j) * N + bx + tx];
    __syncthreads();
    #pragma unroll
    for (int j = 0; j < 32; j += 8)
        out[(size_t)(bx + ty + j) * K + by + tx] = __float2half(tile[tx][ty + j]);
}

// ---------------------------------------------------------------------------
// fp16 tensor GEMM: C[M,N] = A[M,K] @ Bt[N,K]^T (+bias).
// 128x128x32 tile, 256 threads (8 warps, warp tile 32x64), cp.async 2-stage.
// A smem [m][k] stride 40, Bt smem [n][k] stride 40 (conflict-free LDS.32).
// ---------------------------------------------------------------------------
template<bool BIAS, bool HALFOUT>
__global__ void __launch_bounds__(256) gemm_fp16(
    const __half* __restrict__ A, const __half* __restrict__ Bt,
    const float* __restrict__ bias, void* __restrict__ Cv,
    int M, int N, int K)
{
    __shared__ __half As[2][128][40];
    __shared__ __half Bs[2][128][40];

    const int t    = threadIdx.x;
    const int lane = t & 31;
    const int warp = t >> 5;
    const int wm   = warp >> 1;        // 0..3
    const int wn   = warp & 1;         // 0..1
    const int g    = lane >> 2;
    const int tg   = lane & 3;
    const int bm   = blockIdx.y * 128;
    const int bn   = blockIdx.x * 128;

    float acc[2][8][4];
    #pragma unroll
    for (int mt = 0; mt < 2; mt++)
        #pragma unroll
        for (int nt = 0; nt < 8; nt++)
            #pragma unroll
            for (int i = 0; i < 4; i++) acc[mt][nt][i] = 0.f;

    auto prefetch = [&](int s, int k0) {
        #pragma unroll
        for (int i = 0; i < 2; i++) {
            int v = t + 256 * i;
            int r = v >> 2, c = (v & 3) * 8;
            cp16(&As[s][r][c], A + (size_t)(bm + r) * K + k0 + c);
        }
        #pragma unroll
        for (int i = 0; i < 2; i++) {
            int v = t + 256 * i;
            int r = v >> 2, c = (v & 3) * 8;
            cp16(&Bs[s][r][c], Bt + (size_t)(bn + r) * K + k0 + c);
        }
    };

    const int KT = K >> 5;
    prefetch(0, 0);
    CP_COMMIT();

    for (int kt = 0; kt < KT; kt++) {
        CP_WAIT0();
        __syncthreads();
        if (kt + 1 < KT) { prefetch((kt + 1) & 1, (kt + 1) * 32); CP_COMMIT(); }

        const int buf = kt & 1;
        #pragma unroll
        for (int kd = 0; kd < 2; kd++) {          // two K=16 steps
            unsigned af[2][4], bf[8][2];
            #pragma unroll
            for (int mt = 0; mt < 2; mt++) {
                int r = wm * 32 + mt * 16 + g;
                int c = kd * 16 + 2 * tg;
                af[mt][0] = *(const unsigned*)&As[buf][r][c];
                af[mt][1] = *(const unsigned*)&As[buf][r + 8][c];
                af[mt][2] = *(const unsigned*)&As[buf][r][c + 8];
                af[mt][3] = *(const unsigned*)&As[buf][r + 8][c + 8];
            }
            #pragma unroll
            for (int nt = 0; nt < 8; nt++) {
                int n = wn * 64 + nt * 8 + g;
                int c = kd * 16 + 2 * tg;
                bf[nt][0] = *(const unsigned*)&Bs[buf][n][c];
                bf[nt][1] = *(const unsigned*)&Bs[buf][n][c + 8];
            }
            #pragma unroll
            for (int mt = 0; mt < 2; mt++)
                #pragma unroll
                for (int nt = 0; nt < 8; nt++)
                    mma16(acc[mt][nt], af[mt], bf[nt]);
        }
        __syncthreads();
    }

    #pragma unroll
    for (int mt = 0; mt < 2; mt++) {
        int r0 = bm + wm * 32 + mt * 16 + g;
        #pragma unroll
        for (int nt = 0; nt < 8; nt++) {
            int cc = bn + wn * 64 + nt * 8 + tg * 2;
            float2 v0 = make_float2(acc[mt][nt][0], acc[mt][nt][1]);
            float2 v1 = make_float2(acc[mt][nt][2], acc[mt][nt][3]);
            if (BIAS) {
                float2 bb = *(const float2*)(bias + cc);
                v0.x += bb.x; v0.y += bb.y;
                v1.x += bb.x; v1.y += bb.y;
            }
            if (HALFOUT) {
                __half* C = (__half*)Cv;
                *(unsigned*)(C + (size_t)r0 * N + cc)       = pack2(v0.x, v0.y);
                *(unsigned*)(C + (size_t)(r0 + 8) * N + cc) = pack2(v1.x, v1.y);
            } else {
                float* C = (float*)Cv;
                *(float2*)(C + (size_t)r0 * N + cc)       = v0;
                *(float2*)(C + (size_t)(r0 + 8) * N + cc) = v1;
            }
        }
    }
}

// ---------------------------------------------------------------------------
// Flash attention, fp16 m16n8k16. 128 threads (4 warps), warp = 16 q-rows,
// 64-key tiles, cp.async 2-stage. P packs straight into A-fragments (no
// shuffles); V B-fragments via ldmatrix.x4.trans.
// ---------------------------------------------------------------------------
__global__ void __launch_bounds__(128) attn_fp16(
    const __half* __restrict__ qkv, __half* __restrict__ out)
{
    __shared__ __half Ks[2][64][72];
    __shared__ __half Vs[2][64][72];

    const int t    = threadIdx.x;
    const int lane = t & 31;
    const int warp = t >> 5;
    const int g    = lane >> 2;
    const int tg   = lane & 3;
    const int qt   = blockIdx.x;
    const int bh   = blockIdx.y;
    const int b    = bh / NHEAD;
    const int h    = bh - b * NHEAD;
    const size_t rs = 3 * DIMC;

    const __half* kvb = qkv + (size_t)(b * NTOK) * rs + DIMC + h * HDIM;

    auto prefetch_kv = [&](int s, int kt) {
        const __half* kb = kvb + (size_t)(kt * 64) * rs;
        #pragma unroll
        for (int i = 0; i < 4; i++) {
            int v = t + 128 * i;
            int r = v >> 3, c = (v & 7) * 8;
            const __half* rp = kb + (size_t)r * rs;
            cp16(&Ks[s][r][c], rp + c);
            cp16(&Vs[s][r][c], rp + DIMC + c);
        }
    };

    prefetch_kv(0, 0);
    CP_COMMIT();

    // stage scaled Q through Vs[1] (free until prefetch(1) inside the loop)
    {
        __half* qs = &Vs[1][0][0];
        const __half* qbase = qkv + (size_t)(b * NTOK + qt * 64) * rs + h * HDIM;
        const __half2 sc = __float2half2_rn(0.125f);
        #pragma unroll
        for (int i = 0; i < 4; i++) {
            int v = t + 128 * i;
            int r = v >> 3, c = (v & 7) * 8;
            uint4 raw = *(const uint4*)(qbase + (size_t)r * rs + c);
            __half2* hp = (__half2*)&raw;
            hp[0] = __hmul2(hp[0], sc);
            hp[1] = __hmul2(hp[1], sc);
            hp[2] = __hmul2(hp[2], sc);
            hp[3] = __hmul2(hp[3], sc);
            *(uint4*)(qs + r * 72 + c) = raw;
        }
    }
    __syncthreads();

    unsigned qa[4][4];   // 4 K=16 steps over d=64
    {
        const __half* qs = &Vs[1][0][0];
        int r = warp * 16 + g;
        #pragma unroll
        for (int kd = 0; kd < 4; kd++) {
            int c = kd * 16 + 2 * tg;
            qa[kd][0] = *(const unsigned*)&qs[r * 72 + c];
            qa[kd][1] = *(const unsigned*)&qs[(r + 8) * 72 + c];
            qa[kd][2] = *(const unsigned*)&qs[r * 72 + c + 8];
            qa[kd][3] = *(const unsigned*)&qs[(r + 8) * 72 + c + 8];
        }
    }

    float oacc[8][4];
    #pragma unroll
    for (int dt = 0; dt < 8; dt++)
        #pragma unroll
        for (int i = 0; i < 4; i++) oacc[dt][i] = 0.f;

    float m0 = -1e30f, m1 = -1e30f, l0 = 0.f, l1 = 0.f;

    for (int kt = 0; kt < 16; kt++) {
        CP_WAIT0();
        __syncthreads();
        if (kt + 1 < 16) { prefetch_kv((kt + 1) & 1, kt + 1); CP_COMMIT(); }

        const int buf = kt & 1;

        // ---- S = Q @ K^T : 16 rows x 64 keys ----
        float sacc[8][4];
        #pragma unroll
        for (int nt = 0; nt < 8; nt++)
            #pragma unroll
            for (int i = 0; i < 4; i++) sacc[nt][i] = 0.f;

        #pragma unroll
        for (int kd = 0; kd < 4; kd++) {
            int c = kd * 16 + 2 * tg;
            #pragma unroll
            for (int nt = 0; nt < 8; nt++) {
                int key = nt * 8 + g;
                unsigned bf[2];
                bf[0] = *(const unsigned*)&Ks[buf][key][c];
                bf[1] = *(const unsigned*)&Ks[buf][key][c + 8];
                mma16(sacc[nt], qa[kd], bf);
            }
        }

        // ---- online softmax ----
        float mx0 = -1e30f, mx1 = -1e30f;
        #pragma unroll
        for (int nt = 0; nt < 8; nt++) {
            mx0 = fmaxf(mx0, fmaxf(sacc[nt][0], sacc[nt][1]));
            mx1 = fmaxf(mx1, fmaxf(sacc[nt][2], sacc[nt][3]));
        }
        mx0 = fmaxf(mx0, __shfl_xor_sync(0xFFFFFFFFu, mx0, 1));
        mx0 = fmaxf(mx0, __shfl_xor_sync(0xFFFFFFFFu, mx0, 2));
        mx1 = fmaxf(mx1, __shfl_xor_sync(0xFFFFFFFFu, mx1, 1));
        mx1 = fmaxf(mx1, __shfl_xor_sync(0xFFFFFFFFu, mx1, 2));

        float nm0 = fmaxf(m0, mx0), nm1 = fmaxf(m1, mx1);
        float a0 = __expf(m0 - nm0), a1 = __expf(m1 - nm1);
        m0 = nm0; m1 = nm1;

        float s0 = 0.f, s1 = 0.f;
        unsigned pa[4][4];   // A-fragments of P: [16-key block][4 regs]
        #pragma unroll
        for (int j = 0; j < 4; j++) {
            #pragma unroll
            for (int half = 0; half < 2; half++) {
                int nt = 2 * j + half;
                float p0 = __expf(sacc[nt][0] - m0);
                float p1 = __expf(sacc[nt][1] - m0);
                float p2 = __expf(sacc[nt][2] - m1);
                float p3 = __expf(sacc[nt][3] - m1);
                s0 += p0 + p1;
                s1 += p2 + p3;
                pa[j][half * 2 + 0] = pack2(p0, p1);   // rows g   (k 0-7 / 8-15)
                pa[j][half * 2 + 1] = pack2(p2, p3);   // rows g+8
            }
        }
        // fragment order: {r0,r1} = k 0-7 rows g/g+8 ; {r2,r3} = k 8-15
        // pa[j] = {pack(ntA c0c1), pack(ntA c2c3), pack(ntB c0c1), pack(ntB c2c3)} ✓

        s0 += __shfl_xor_sync(0xFFFFFFFFu, s0, 1);
        s0 += __shfl_xor_sync(0xFFFFFFFFu, s0, 2);
        s1 += __shfl_xor_sync(0xFFFFFFFFu, s1, 1);
        s1 += __shfl_xor_sync(0xFFFFFFFFu, s1, 2);
        l0 = l0 * a0 + s0;
        l1 = l1 * a1 + s1;
        #pragma unroll
        for (int dt = 0; dt < 8; dt++) {
            oacc[dt][0] *= a0; oacc[dt][1] *= a0;
            oacc[dt][2] *= a1; oacc[dt][3] *= a1;
        }

        // ---- O += P @ V via ldmatrix.x4.trans B-fragments ----
        unsigned vbase = (unsigned)__cvta_generic_to_shared(&Vs[buf][0][0]);
        int mrow = lane & 7;
        int msel = lane >> 3;            // matrix index 0..3
        #pragma unroll
        for (int j = 0; j < 4; j++) {    // 16-key blocks
            #pragma unroll
            for (int dp = 0; dp < 4; dp++) {   // 16-col blocks
                int row = j * 16 + (msel & 1) * 8 + mrow;
                int col = dp * 16 + (msel >> 1) * 8;
                unsigned r[4];
                ldmx4t(r, vbase + (unsigned)(row * 72 + col) * 2);
                mma16(oacc[dp * 2 + 0], pa[j], r);
                mma16(oacc[dp * 2 + 1], pa[j], r + 2);
            }
        }
    }

    // ---- epilogue: normalize, store half ----
    float inv0 = 1.0f / l0, inv1 = 1.0f / l1;
    int token = b * NTOK + qt * 64 + warp * 16 + g;
    __half* op = out + (size_t)token * DIMC + h * HDIM;
    #pragma unroll
    for (int dt = 0; dt < 8; dt++) {
        int d = dt * 8 + tg * 2;
        *(unsigned*)(op + d)            = pack2(oacc[dt][0] * inv0, oacc[dt][1] * inv0);
        *(unsigned*)(op + 8 * DIMC + d) = pack2(oacc[dt][2] * inv1, oacc[dt][3] * inv1);
    }
}

// ---------------------------------------------------------------------------
// kernel_launch
// ---------------------------------------------------------------------------
extern "C" void kernel_launch(void* const* d_in, const int* in_sizes, int n_in,
                              void* d_out, int out_size)
{
    const float* x      = (const float*)d_in[0];
    const float* w_qkv  = (const float*)d_in[1];
    const float* w_proj = (const float*)d_in[2];
    const float* b_proj = (const float*)d_in[3];
    float*       out    = (float*)d_out;

    void *qkv_p, *attn_p, *x_p, *wqkvT_p, *wprojT_p;
    cudaGetSymbolAddress(&qkv_p,   g_qkv);
    cudaGetSymbolAddress(&attn_p,  g_attn);
    cudaGetSymbolAddress(&x_p,     g_x);
    cudaGetSymbolAddress(&wqkvT_p, g_wqkvT);
    cudaGetSymbolAddress(&wprojT_p,g_wprojT);

    // 0) prep: x -> half; weights -> transposed half [N][K]
    {
        int n4x = MTOK * DIMC / 4;
        conv_half<<<(n4x + 255) / 256, 256>>>((const float4*)x, (__half*)x_p, n4x);
        transpose_half<<<dim3(3 * DIMC / 32, DIMC / 32), 256>>>(
            w_qkv, (__half*)wqkvT_p, DIMC, 3 * DIMC);
        transpose_half<<<dim3(DIMC / 32, DIMC / 32), 256>>>(
            w_proj, (__half*)wprojT_p, DIMC, DIMC);
    }

    // 1) QKV GEMM: [8192,768] @ [768,2304] -> half
    gemm_fp16<false, true><<<dim3(3 * DIMC / 128, MTOK / 128), 256>>>(
        (const __half*)x_p, (const __half*)wqkvT_p, nullptr, qkv_p,
        MTOK, 3 * DIMC, DIMC);

    // 2) Attention -> half
    attn_fp16<<<dim3(NTOK / 64, NBATCH * NHEAD), 128>>>(
        (const __half*)qkv_p, (__half*)attn_p);

    // 3) Projection + bias -> fp32 output
    gemm_fp16<true, false><<<dim3(DIMC / 128, MTOK / 128), 256>>>(
        (const __half*)attn_p, (const __half*)wprojT_p, b_proj, (void*)out,
        MTOK, DIMC, DIMC);
}

// round 7
// speedup vs baseline: 2.1096x; 1.0531x over previous
#include <cuda_runtime.h>
#include <cuda_fp16.h>
#include <cstdint>

#define DIMC   768
#define NHEAD  12
#define HDIM   64
#define NBATCH 8
#define NTOK   1024
#define MTOK   (NBATCH * NTOK)

// Scratch (allocation-free), all fp16
__device__ __half g_qkv[(size_t)MTOK * 3 * DIMC];
__device__ __half g_attn[(size_t)MTOK * DIMC];
__device__ __half g_x[(size_t)MTOK * DIMC];
__device__ __half g_wqkvT[(size_t)3 * DIMC * DIMC];
__device__ __half g_wprojT[(size_t)DIMC * DIMC];

// ---------------------------------------------------------------------------
// helpers
// ---------------------------------------------------------------------------
__device__ __forceinline__ unsigned pack2(float a, float b) {
    __half2 h = __floats2half2_rn(a, b);
    return *(unsigned*)&h;
}

__device__ __forceinline__ void mma16(float* d, const unsigned* a, const unsigned* b) {
    asm volatile(
        "mma.sync.aligned.m16n8k16.row.col.f32.f16.f16.f32 "
        "{%0,%1,%2,%3},{%4,%5,%6,%7},{%8,%9},{%0,%1,%2,%3};\n"
        : "+f"(d[0]), "+f"(d[1]), "+f"(d[2]), "+f"(d[3])
        : "r"(a[0]), "r"(a[1]), "r"(a[2]), "r"(a[3]),
          "r"(b[0]), "r"(b[1]));
}

__device__ __forceinline__ void cp16(void* sdst, const void* gsrc) {
    unsigned sa = (unsigned)__cvta_generic_to_shared(sdst);
    asm volatile("cp.async.cg.shared.global [%0], [%1], 16;\n" :: "r"(sa), "l"(gsrc));
}
#define CP_COMMIT() asm volatile("cp.async.commit_group;\n" ::: "memory")
#define CP_WAIT0()  asm volatile("cp.async.wait_group 0;\n" ::: "memory")
#define CP_WAIT1()  asm volatile("cp.async.wait_group 1;\n" ::: "memory")

__device__ __forceinline__ void ldmx4(unsigned* r, const void* p) {
    unsigned sa = (unsigned)__cvta_generic_to_shared(p);
    asm volatile(
        "ldmatrix.sync.aligned.m8n8.x4.shared.b16 {%0,%1,%2,%3}, [%4];"
        : "=r"(r[0]), "=r"(r[1]), "=r"(r[2]), "=r"(r[3]) : "r"(sa));
}
__device__ __forceinline__ void ldmx4t(unsigned* r, const void* p) {
    unsigned sa = (unsigned)__cvta_generic_to_shared(p);
    asm volatile(
        "ldmatrix.sync.aligned.m8n8.x4.trans.shared.b16 {%0,%1,%2,%3}, [%4];"
        : "=r"(r[0]), "=r"(r[1]), "=r"(r[2]), "=r"(r[3]) : "r"(sa));
}

// ---------------------------------------------------------------------------
// prep kernels
// ---------------------------------------------------------------------------
__global__ void __launch_bounds__(256) conv_half(
    const float4* __restrict__ in, __half* __restrict__ out, int n4)
{
    int i = blockIdx.x * 256 + threadIdx.x;
    if (i < n4) {
        float4 v = in[i];
        uint2 u;
        u.x = pack2(v.x, v.y);
        u.y = pack2(v.z, v.w);
        *(uint2*)(out + 4 * (size_t)i) = u;
    }
}

__global__ void __launch_bounds__(256) transpose_half(
    const float* __restrict__ in, __half* __restrict__ out, int K, int N)
{
    __shared__ float tile[32][33];
    int bx = blockIdx.x * 32;
    int by = blockIdx.y * 32;
    int tx = threadIdx.x & 31, ty = threadIdx.x >> 5;
    #pragma unroll
    for (int j = 0; j < 32; j += 8)
        tile[ty + j][tx] = in[(size_t)(by + ty + j) * N + bx + tx];
    __syncthreads();
    #pragma unroll
    for (int j = 0; j < 32; j += 8)
        out[(size_t)(bx + ty + j) * K + by + tx] = __float2half(tile[tx][ty + j]);
}

// ---------------------------------------------------------------------------
// fp16 GEMM: C[M,N] = A[M,K] @ Bt[N,K]^T (+bias). 128x128x32 tile, 256 thr,
// warp tile 32x64, 3-stage cp.async ring, ldmatrix.x4 fragment loads.
// smem rows stride 40 halves (80B) -> conflict-free ldmatrix phases.
// ---------------------------------------------------------------------------
#define GST   (128 * 40)                 // halves per stage per operand
#define GEMM_SMEM (3 * GST * 2 * 2)      // 3 stages, A+B, 2 bytes

template<bool BIAS, bool HALFOUT>
__global__ void __launch_bounds__(256) gemm_fp16(
    const __half* __restrict__ A, const __half* __restrict__ Bt,
    const float* __restrict__ bias, void* __restrict__ Cv,
    int M, int N, int K)
{
    extern __shared__ __half smh[];
    __half* As = smh;              // [3][128][40]
    __half* Bs = smh + 3 * GST;    // [3][128][40]

    const int t    = threadIdx.x;
    const int lane = t & 31;
    const int warp = t >> 5;
    const int wm   = warp >> 1;
    const int wn   = warp & 1;
    const int g    = lane >> 2;
    const int tg   = lane & 3;
    const int bm   = blockIdx.y * 128;
    const int bn   = blockIdx.x * 128;

    // ldmatrix per-lane address offsets
    const int a_row = lane & 15;
    const int a_col = (lane >> 4) << 3;          // 0 or 8
    const int b_row = (lane & 7) | ((lane & 16) >> 1);
    const int b_col = lane & 8;

    float acc[2][8][4];
    #pragma unroll
    for (int mt = 0; mt < 2; mt++)
        #pragma unroll
        for (int nt = 0; nt < 8; nt++)
            #pragma unroll
            for (int i = 0; i < 4; i++) acc[mt][nt][i] = 0.f;

    auto prefetch = [&](int s, int k0) {
        __half* as = As + s * GST;
        __half* bs = Bs + s * GST;
        #pragma unroll
        for (int i = 0; i < 2; i++) {
            int v = t + 256 * i;
            int r = v >> 2, c = (v & 3) * 8;
            cp16(as + r * 40 + c, A + (size_t)(bm + r) * K + k0 + c);
        }
        #pragma unroll
        for (int i = 0; i < 2; i++) {
            int v = t + 256 * i;
            int r = v >> 2, c = (v & 3) * 8;
            cp16(bs + r * 40 + c, Bt + (size_t)(bn + r) * K + k0 + c);
        }
    };

    const int KT = K >> 5;
    prefetch(0, 0);  CP_COMMIT();
    prefetch(1, 32); CP_COMMIT();

    int st = 0;
    for (int kt = 0; kt < KT; kt++) {
        if (kt + 1 < KT) { CP_WAIT1(); } else { CP_WAIT0(); }
        __syncthreads();
        if (kt + 2 < KT) {
            int ps = st + 2; if (ps >= 3) ps -= 3;
            prefetch(ps, (kt + 2) * 32);
            CP_COMMIT();
        }

        const __half* as = As + st * GST;
        const __half* bs = Bs + st * GST;

        #pragma unroll
        for (int kd = 0; kd < 2; kd++) {
            int c = kd * 16;
            unsigned af[2][4], bf[4][4];
            ldmx4(af[0], &as[(wm * 32 + a_row) * 40 + c + a_col]);
            ldmx4(af[1], &as[(wm * 32 + 16 + a_row) * 40 + c + a_col]);
            #pragma unroll
            for (int j = 0; j < 4; j++)
                ldmx4(bf[j], &bs[(wn * 64 + j * 16 + b_row) * 40 + c + b_col]);
            #pragma unroll
            for (int mt = 0; mt < 2; mt++)
                #pragma unroll
                for (int nt = 0; nt < 8; nt++)
                    mma16(acc[mt][nt], af[mt], &bf[nt >> 1][(nt & 1) * 2]);
        }
        if (++st == 3) st = 0;
    }

    #pragma unroll
    for (int mt = 0; mt < 2; mt++) {
        int r0 = bm + wm * 32 + mt * 16 + g;
        #pragma unroll
        for (int nt = 0; nt < 8; nt++) {
            int cc = bn + wn * 64 + nt * 8 + tg * 2;
            float2 v0 = make_float2(acc[mt][nt][0], acc[mt][nt][1]);
            float2 v1 = make_float2(acc[mt][nt][2], acc[mt][nt][3]);
            if (BIAS) {
                float2 bb = *(const float2*)(bias + cc);
                v0.x += bb.x; v0.y += bb.y;
                v1.x += bb.x; v1.y += bb.y;
            }
            if (HALFOUT) {
                __half* C = (__half*)Cv;
                *(unsigned*)(C + (size_t)r0 * N + cc)       = pack2(v0.x, v0.y);
                *(unsigned*)(C + (size_t)(r0 + 8) * N + cc) = pack2(v1.x, v1.y);
            } else {
                float* C = (float*)Cv;
                *(float2*)(C + (size_t)r0 * N + cc)       = v0;
                *(float2*)(C + (size_t)(r0 + 8) * N + cc) = v1;
            }
        }
    }
}

// ---------------------------------------------------------------------------
// Flash attention fp16, ldmatrix for K and V fragments, cp.async 2-stage.
// 128 threads, warp = 16 q-rows, 64-key tiles.
// ---------------------------------------------------------------------------
__global__ void __launch_bounds__(128) attn_fp16(
    const __half* __restrict__ qkv, __half* __restrict__ out)
{
    __shared__ __half Ks[2][64][72];
    __shared__ __half Vs[2][64][72];

    const int t    = threadIdx.x;
    const int lane = t & 31;
    const int warp = t >> 5;
    const int g    = lane >> 2;
    const int tg   = lane & 3;
    const int qt   = blockIdx.x;
    const int bh   = blockIdx.y;
    const int b    = bh / NHEAD;
    const int h    = bh - b * NHEAD;
    const size_t rs = 3 * DIMC;

    const int b_row = (lane & 7) | ((lane & 16) >> 1);
    const int b_col = lane & 8;

    const __half* kvb = qkv + (size_t)(b * NTOK) * rs + DIMC + h * HDIM;

    auto prefetch_kv = [&](int s, int kt) {
        const __half* kb = kvb + (size_t)(kt * 64) * rs;
        #pragma unroll
        for (int i = 0; i < 4; i++) {
            int v = t + 128 * i;
            int r = v >> 3, c = (v & 7) * 8;
            const __half* rp = kb + (size_t)r * rs;
            cp16(&Ks[s][r][c], rp + c);
            cp16(&Vs[s][r][c], rp + DIMC + c);
        }
    };

    prefetch_kv(0, 0);
    CP_COMMIT();

    // stage scaled Q through Vs[1]
    {
        __half* qs = &Vs[1][0][0];
        const __half* qbase = qkv + (size_t)(b * NTOK + qt * 64) * rs + h * HDIM;
        const __half2 sc = __float2half2_rn(0.125f);
        #pragma unroll
        for (int i = 0; i < 4; i++) {
            int v = t + 128 * i;
            int r = v >> 3, c = (v & 7) * 8;
            uint4 raw = *(const uint4*)(qbase + (size_t)r * rs + c);
            __half2* hp = (__half2*)&raw;
            hp[0] = __hmul2(hp[0], sc);
            hp[1] = __hmul2(hp[1], sc);
            hp[2] = __hmul2(hp[2], sc);
            hp[3] = __hmul2(hp[3], sc);
            *(uint4*)(qs + r * 72 + c) = raw;
        }
    }
    __syncthreads();

    unsigned qa[4][4];
    {
        const __half* qs = &Vs[1][0][0];
        const int a_row = lane & 15;
        const int a_col = (lane >> 4) << 3;
        #pragma unroll
        for (int kd = 0; kd < 4; kd++)
            ldmx4(qa[kd], &qs[(warp * 16 + a_row) * 72 + kd * 16 + a_col]);
    }

    float oacc[8][4];
    #pragma unroll
    for (int dt = 0; dt < 8; dt++)
        #pragma unroll
        for (int i = 0; i < 4; i++) oacc[dt][i] = 0.f;

    float m0 = -1e30f, m1 = -1e30f, l0 = 0.f, l1 = 0.f;

    for (int kt = 0; kt < 16; kt++) {
        CP_WAIT0();
        __syncthreads();
        if (kt + 1 < 16) { prefetch_kv((kt + 1) & 1, kt + 1); CP_COMMIT(); }

        const int buf = kt & 1;

        // ---- S = Q @ K^T : 16 rows x 64 keys ----
        float sacc[8][4];
        #pragma unroll
        for (int nt = 0; nt < 8; nt++)
            #pragma unroll
            for (int i = 0; i < 4; i++) sacc[nt][i] = 0.f;

        #pragma unroll
        for (int kd = 0; kd < 4; kd++) {
            int c = kd * 16;
            unsigned kf[4][4];
            #pragma unroll
            for (int j = 0; j < 4; j++)
                ldmx4(kf[j], &Ks[buf][j * 16 + b_row][c + b_col]);
            #pragma unroll
            for (int nt = 0; nt < 8; nt++)
                mma16(sacc[nt], qa[kd], &kf[nt >> 1][(nt & 1) * 2]);
        }

        // ---- online softmax ----
        float mx0 = -1e30f, mx1 = -1e30f;
        #pragma unroll
        for (int nt = 0; nt < 8; nt++) {
            mx0 = fmaxf(mx0, fmaxf(sacc[nt][0], sacc[nt][1]));
            mx1 = fmaxf(mx1, fmaxf(sacc[nt][2], sacc[nt][3]));
        }
        mx0 = fmaxf(mx0, __shfl_xor_sync(0xFFFFFFFFu, mx0, 1));
        mx0 = fmaxf(mx0, __shfl_xor_sync(0xFFFFFFFFu, mx0, 2));
        mx1 = fmaxf(mx1, __shfl_xor_sync(0xFFFFFFFFu, mx1, 1));
        mx1 = fmaxf(mx1, __shfl_xor_sync(0xFFFFFFFFu, mx1, 2));

        float nm0 = fmaxf(m0, mx0), nm1 = fmaxf(m1, mx1);
        float a0 = __expf(m0 - nm0), a1 = __expf(m1 - nm1);
        m0 = nm0; m1 = nm1;

        float s0 = 0.f, s1 = 0.f;
        unsigned pa[4][4];
        #pragma unroll
        for (int j = 0; j < 4; j++) {
            #pragma unroll
            for (int hv = 0; hv < 2; hv++) {
                int nt = 2 * j + hv;
                float p0 = __expf(sacc[nt][0] - m0);
                float p1 = __expf(sacc[nt][1] - m0);
                float p2 = __expf(sacc[nt][2] - m1);
                float p3 = __expf(sacc[nt][3] - m1);
                s0 += p0 + p1;
                s1 += p2 + p3;
                pa[j][hv * 2 + 0] = pack2(p0, p1);
                pa[j][hv * 2 + 1] = pack2(p2, p3);
            }
        }

        s0 += __shfl_xor_sync(0xFFFFFFFFu, s0, 1);
        s0 += __shfl_xor_sync(0xFFFFFFFFu, s0, 2);
        s1 += __shfl_xor_sync(0xFFFFFFFFu, s1, 1);
        s1 += __shfl_xor_sync(0xFFFFFFFFu, s1, 2);
        l0 = l0 * a0 + s0;
        l1 = l1 * a1 + s1;
        #pragma unroll
        for (int dt = 0; dt < 8; dt++) {
            oacc[dt][0] *= a0; oacc[dt][1] *= a0;
            oacc[dt][2] *= a1; oacc[dt][3] *= a1;
        }

        // ---- O += P @ V (ldmatrix.x4.trans B-fragments) ----
        int mrow = lane & 7;
        int msel = lane >> 3;
        #pragma unroll
        for (int j = 0; j < 4; j++) {
            #pragma unroll
            for (int dp = 0; dp < 4; dp++) {
                int row = j * 16 + (msel & 1) * 8 + mrow;
                int col = dp * 16 + (msel >> 1) * 8;
                unsigned r[4];
                ldmx4t(r, &Vs[buf][row][col]);
                mma16(oacc[dp * 2 + 0], pa[j], r);
                mma16(oacc[dp * 2 + 1], pa[j], r + 2);
            }
        }
    }

    // ---- epilogue ----
    float inv0 = 1.0f / l0, inv1 = 1.0f / l1;
    int token = b * NTOK + qt * 64 + warp * 16 + g;
    __half* op = out + (size_t)token * DIMC + h * HDIM;
    #pragma unroll
    for (int dt = 0; dt < 8; dt++) {
        int d = dt * 8 + tg * 2;
        *(unsigned*)(op + d)            = pack2(oacc[dt][0] * inv0, oacc[dt][1] * inv0);
        *(unsigned*)(op + 8 * DIMC + d) = pack2(oacc[dt][2] * inv1, oacc[dt][3] * inv1);
    }
}

// ---------------------------------------------------------------------------
// kernel_launch
// ---------------------------------------------------------------------------
extern "C" void kernel_launch(void* const* d_in, const int* in_sizes, int n_in,
                              void* d_out, int out_size)
{
    const float* x      = (const float*)d_in[0];
    const float* w_qkv  = (const float*)d_in[1];
    const float* w_proj = (const float*)d_in[2];
    const float* b_proj = (const float*)d_in[3];
    float*       out    = (float*)d_out;

    void *qkv_p, *attn_p, *x_p, *wqkvT_p, *wprojT_p;
    cudaGetSymbolAddress(&qkv_p,   g_qkv);
    cudaGetSymbolAddress(&attn_p,  g_attn);
    cudaGetSymbolAddress(&x_p,     g_x);
    cudaGetSymbolAddress(&wqkvT_p, g_wqkvT);
    cudaGetSymbolAddress(&wprojT_p,g_wprojT);

    static bool attr_set = false;
    if (!attr_set) {
        cudaFuncSetAttribute((const void*)gemm_fp16<false, true>,
                             cudaFuncAttributeMaxDynamicSharedMemorySize, GEMM_SMEM);
        cudaFuncSetAttribute((const void*)gemm_fp16<true, false>,
                             cudaFuncAttributeMaxDynamicSharedMemorySize, GEMM_SMEM);
        attr_set = true;
    }

    // 0) prep
    {
        int n4x = MTOK * DIMC / 4;
        conv_half<<<(n4x + 255) / 256, 256>>>((const float4*)x, (__half*)x_p, n4x);
        transpose_half<<<dim3(3 * DIMC / 32, DIMC / 32), 256>>>(
            w_qkv, (__half*)wqkvT_p, DIMC, 3 * DIMC);
        transpose_half<<<dim3(DIMC / 32, DIMC / 32), 256>>>(
            w_proj, (__half*)wprojT_p, DIMC, DIMC);
    }

    // 1) QKV GEMM
    gemm_fp16<false, true><<<dim3(3 * DIMC / 128, MTOK / 128), 256, GEMM_SMEM>>>(
        (const __half*)x_p, (const __half*)wqkvT_p, nullptr, qkv_p,
        MTOK, 3 * DIMC, DIMC);

    // 2) Attention
    attn_fp16<<<dim3(NTOK / 64, NBATCH * NHEAD), 128>>>(
        (const __half*)qkv_p, (__half*)attn_p);

    // 3) Projection + bias
    gemm_fp16<true, false><<<dim3(DIMC / 128, MTOK / 128), 256, GEMM_SMEM>>>(
        (const __half*)attn_p, (const __half*)wprojT_p, b_proj, (void*)out,
        MTOK, DIMC, DIMC);
}

// round 8
// speedup vs baseline: 2.3570x; 1.1173x over previous
#include <cuda_runtime.h>
#include <cuda_fp16.h>
#include <cstdint>

#define DIMC   768
#define NHEAD  12
#define HDIM   64
#define NBATCH 8
#define NTOK   1024
#define MTOK   (NBATCH * NTOK)

// Scratch (allocation-free), all fp16
__device__ __half g_qkv[(size_t)MTOK * 3 * DIMC];
__device__ __half g_attn[(size_t)MTOK * DIMC];
__device__ __half g_x[(size_t)MTOK * DIMC];
__device__ __half g_wqkvT[(size_t)3 * DIMC * DIMC];
__device__ __half g_wprojT[(size_t)DIMC * DIMC];

// ---------------------------------------------------------------------------
// helpers
// ---------------------------------------------------------------------------
__device__ __forceinline__ unsigned pack2(float a, float b) {
    __half2 h = __floats2half2_rn(a, b);
    return *(unsigned*)&h;
}

__device__ __forceinline__ void mma16(float* d, const unsigned* a, const unsigned* b) {
    asm volatile(
        "mma.sync.aligned.m16n8k16.row.col.f32.f16.f16.f32 "
        "{%0,%1,%2,%3},{%4,%5,%6,%7},{%8,%9},{%0,%1,%2,%3};\n"
        : "+f"(d[0]), "+f"(d[1]), "+f"(d[2]), "+f"(d[3])
        : "r"(a[0]), "r"(a[1]), "r"(a[2]), "r"(a[3]),
          "r"(b[0]), "r"(b[1]));
}

__device__ __forceinline__ void cp16(void* sdst, const void* gsrc) {
    unsigned sa = (unsigned)__cvta_generic_to_shared(sdst);
    asm volatile("cp.async.cg.shared.global [%0], [%1], 16;\n" :: "r"(sa), "l"(gsrc));
}
#define CP_COMMIT() asm volatile("cp.async.commit_group;\n" ::: "memory")
#define CP_WAIT0()  asm volatile("cp.async.wait_group 0;\n" ::: "memory")
#define CP_WAIT1()  asm volatile("cp.async.wait_group 1;\n" ::: "memory")

__device__ __forceinline__ void ldmx4(unsigned* r, const void* p) {
    unsigned sa = (unsigned)__cvta_generic_to_shared(p);
    asm volatile(
        "ldmatrix.sync.aligned.m8n8.x4.shared.b16 {%0,%1,%2,%3}, [%4];"
        : "=r"(r[0]), "=r"(r[1]), "=r"(r[2]), "=r"(r[3]) : "r"(sa));
}
__device__ __forceinline__ void ldmx4t(unsigned* r, const void* p) {
    unsigned sa = (unsigned)__cvta_generic_to_shared(p);
    asm volatile(
        "ldmatrix.sync.aligned.m8n8.x4.trans.shared.b16 {%0,%1,%2,%3}, [%4];"
        : "=r"(r[0]), "=r"(r[1]), "=r"(r[2]), "=r"(r[3]) : "r"(sa));
}

// ---------------------------------------------------------------------------
// prep kernels
// ---------------------------------------------------------------------------
__global__ void __launch_bounds__(256) conv_half(
    const float4* __restrict__ in, __half* __restrict__ out, int n4)
{
    int i = blockIdx.x * 256 + threadIdx.x;
    if (i < n4) {
        float4 v = in[i];
        uint2 u;
        u.x = pack2(v.x, v.y);
        u.y = pack2(v.z, v.w);
        *(uint2*)(out + 4 * (size_t)i) = u;
    }
}

__global__ void __launch_bounds__(256) transpose_half(
    const float* __restrict__ in, __half* __restrict__ out, int K, int N)
{
    __shared__ float tile[32][33];
    int bx = blockIdx.x * 32;
    int by = blockIdx.y * 32;
    int tx = threadIdx.x & 31, ty = threadIdx.x >> 5;
    #pragma unroll
    for (int j = 0; j < 32; j += 8)
        tile[ty + j][tx] = in[(size_t)(by + ty + j) * N + bx + tx];
    __syncthreads();
    #pragma unroll
    for (int j = 0; j < 32; j += 8)
        out[(size_t)(bx + ty + j) * K + by + tx] = __float2half(tile[tx][ty + j]);
}

// ---------------------------------------------------------------------------
// fp16 GEMM: C[M,N] = A[M,K] @ Bt[N,K]^T (+bias). 128x128x64 tile, 256 thr,
// warp tile 32x64, 2-stage cp.async, ldmatrix.x4, 128 HMMA per barrier.
// smem rows stride 72 halves (144B) -> conflict-free ldmatrix phases.
// ---------------------------------------------------------------------------
#define GKT   64                          // K-tile depth
#define GST   (128 * 72)                  // halves per stage per operand
#define GEMM_SMEM (2 * GST * 2 * 2)       // 2 stages, A+B, 2 bytes

template<bool BIAS, bool HALFOUT>
__global__ void __launch_bounds__(256) gemm_fp16(
    const __half* __restrict__ A, const __half* __restrict__ Bt,
    const float* __restrict__ bias, void* __restrict__ Cv,
    int M, int N, int K)
{
    extern __shared__ __half smh[];
    __half* As = smh;              // [2][128][72]
    __half* Bs = smh + 2 * GST;    // [2][128][72]

    const int t    = threadIdx.x;
    const int lane = t & 31;
    const int warp = t >> 5;
    const int wm   = warp >> 1;
    const int wn   = warp & 1;
    const int g    = lane >> 2;
    const int tg   = lane & 3;
    const int bm   = blockIdx.y * 128;
    const int bn   = blockIdx.x * 128;

    const int a_row = lane & 15;
    const int a_col = (lane >> 4) << 3;
    const int b_row = (lane & 7) | ((lane & 16) >> 1);
    const int b_col = lane & 8;

    float acc[2][8][4];
    #pragma unroll
    for (int mt = 0; mt < 2; mt++)
        #pragma unroll
        for (int nt = 0; nt < 8; nt++)
            #pragma unroll
            for (int i = 0; i < 4; i++) acc[mt][nt][i] = 0.f;

    auto prefetch = [&](int s, int k0) {
        __half* as = As + s * GST;
        __half* bs = Bs + s * GST;
        #pragma unroll
        for (int i = 0; i < 4; i++) {
            int v = t + 256 * i;
            int r = v >> 3, c = (v & 7) * 8;
            cp16(as + r * 72 + c, A + (size_t)(bm + r) * K + k0 + c);
        }
        #pragma unroll
        for (int i = 0; i < 4; i++) {
            int v = t + 256 * i;
            int r = v >> 3, c = (v & 7) * 8;
            cp16(bs + r * 72 + c, Bt + (size_t)(bn + r) * K + k0 + c);
        }
    };

    const int KT = K / GKT;
    prefetch(0, 0);   CP_COMMIT();
    prefetch(1, GKT); CP_COMMIT();

    for (int kt = 0; kt < KT; kt++) {
        if (kt + 1 < KT) { CP_WAIT1(); } else { CP_WAIT0(); }
        __syncthreads();

        const int buf = kt & 1;
        const __half* as = As + buf * GST;
        const __half* bs = Bs + buf * GST;

        #pragma unroll
        for (int kd = 0; kd < 4; kd++) {
            int c = kd * 16;
            unsigned af[2][4], bf[4][4];
            ldmx4(af[0], &as[(wm * 32 + a_row) * 72 + c + a_col]);
            ldmx4(af[1], &as[(wm * 32 + 16 + a_row) * 72 + c + a_col]);
            #pragma unroll
            for (int j = 0; j < 4; j++)
                ldmx4(bf[j], &bs[(wn * 64 + j * 16 + b_row) * 72 + c + b_col]);
            #pragma unroll
            for (int mt = 0; mt < 2; mt++)
                #pragma unroll
                for (int nt = 0; nt < 8; nt++)
                    mma16(acc[mt][nt], af[mt], &bf[nt >> 1][(nt & 1) * 2]);
        }

        __syncthreads();
        if (kt + 2 < KT) {
            prefetch(buf, (kt + 2) * GKT);
            CP_COMMIT();
        }
    }

    #pragma unroll
    for (int mt = 0; mt < 2; mt++) {
        int r0 = bm + wm * 32 + mt * 16 + g;
        #pragma unroll
        for (int nt = 0; nt < 8; nt++) {
            int cc = bn + wn * 64 + nt * 8 + tg * 2;
            float2 v0 = make_float2(acc[mt][nt][0], acc[mt][nt][1]);
            float2 v1 = make_float2(acc[mt][nt][2], acc[mt][nt][3]);
            if (BIAS) {
                float2 bb = *(const float2*)(bias + cc);
                v0.x += bb.x; v0.y += bb.y;
                v1.x += bb.x; v1.y += bb.y;
            }
            if (HALFOUT) {
                __half* C = (__half*)Cv;
                *(unsigned*)(C + (size_t)r0 * N + cc)       = pack2(v0.x, v0.y);
                *(unsigned*)(C + (size_t)(r0 + 8) * N + cc) = pack2(v1.x, v1.y);
            } else {
                float* C = (float*)Cv;
                *(float2*)(C + (size_t)r0 * N + cc)       = v0;
                *(float2*)(C + (size_t)(r0 + 8) * N + cc) = v1;
            }
        }
    }
}

// ---------------------------------------------------------------------------
// Flash attention fp16 (unchanged from R7)
// ---------------------------------------------------------------------------
__global__ void __launch_bounds__(128) attn_fp16(
    const __half* __restrict__ qkv, __half* __restrict__ out)
{
    __shared__ __half Ks[2][64][72];
    __shared__ __half Vs[2][64][72];

    const int t    = threadIdx.x;
    const int lane = t & 31;
    const int warp = t >> 5;
    const int g    = lane >> 2;
    const int tg   = lane & 3;
    const int qt   = blockIdx.x;
    const int bh   = blockIdx.y;
    const int b    = bh / NHEAD;
    const int h    = bh - b * NHEAD;
    const size_t rs = 3 * DIMC;

    const int b_row = (lane & 7) | ((lane & 16) >> 1);
    const int b_col = lane & 8;

    const __half* kvb = qkv + (size_t)(b * NTOK) * rs + DIMC + h * HDIM;

    auto prefetch_kv = [&](int s, int kt) {
        const __half* kb = kvb + (size_t)(kt * 64) * rs;
        #pragma unroll
        for (int i = 0; i < 4; i++) {
            int v = t + 128 * i;
            int r = v >> 3, c = (v & 7) * 8;
            const __half* rp = kb + (size_t)r * rs;
            cp16(&Ks[s][r][c], rp + c);
            cp16(&Vs[s][r][c], rp + DIMC + c);
        }
    };

    prefetch_kv(0, 0);
    CP_COMMIT();

    {
        __half* qs = &Vs[1][0][0];
        const __half* qbase = qkv + (size_t)(b * NTOK + qt * 64) * rs + h * HDIM;
        const __half2 sc = __float2half2_rn(0.125f);
        #pragma unroll
        for (int i = 0; i < 4; i++) {
            int v = t + 128 * i;
            int r = v >> 3, c = (v & 7) * 8;
            uint4 raw = *(const uint4*)(qbase + (size_t)r * rs + c);
            __half2* hp = (__half2*)&raw;
            hp[0] = __hmul2(hp[0], sc);
            hp[1] = __hmul2(hp[1], sc);
            hp[2] = __hmul2(hp[2], sc);
            hp[3] = __hmul2(hp[3], sc);
            *(uint4*)(qs + r * 72 + c) = raw;
        }
    }
    __syncthreads();

    unsigned qa[4][4];
    {
        const __half* qs = &Vs[1][0][0];
        const int a_row = lane & 15;
        const int a_col = (lane >> 4) << 3;
        #pragma unroll
        for (int kd = 0; kd < 4; kd++)
            ldmx4(qa[kd], &qs[(warp * 16 + a_row) * 72 + kd * 16 + a_col]);
    }

    float oacc[8][4];
    #pragma unroll
    for (int dt = 0; dt < 8; dt++)
        #pragma unroll
        for (int i = 0; i < 4; i++) oacc[dt][i] = 0.f;

    float m0 = -1e30f, m1 = -1e30f, l0 = 0.f, l1 = 0.f;

    for (int kt = 0; kt < 16; kt++) {
        CP_WAIT0();
        __syncthreads();
        if (kt + 1 < 16) { prefetch_kv((kt + 1) & 1, kt + 1); CP_COMMIT(); }

        const int buf = kt & 1;

        float sacc[8][4];
        #pragma unroll
        for (int nt = 0; nt < 8; nt++)
            #pragma unroll
            for (int i = 0; i < 4; i++) sacc[nt][i] = 0.f;

        #pragma unroll
        for (int kd = 0; kd < 4; kd++) {
            int c = kd * 16;
            unsigned kf[4][4];
            #pragma unroll
            for (int j = 0; j < 4; j++)
                ldmx4(kf[j], &Ks[buf][j * 16 + b_row][c + b_col]);
            #pragma unroll
            for (int nt = 0; nt < 8; nt++)
                mma16(sacc[nt], qa[kd], &kf[nt >> 1][(nt & 1) * 2]);
        }

        float mx0 = -1e30f, mx1 = -1e30f;
        #pragma unroll
        for (int nt = 0; nt < 8; nt++) {
            mx0 = fmaxf(mx0, fmaxf(sacc[nt][0], sacc[nt][1]));
            mx1 = fmaxf(mx1, fmaxf(sacc[nt][2], sacc[nt][3]));
        }
        mx0 = fmaxf(mx0, __shfl_xor_sync(0xFFFFFFFFu, mx0, 1));
        mx0 = fmaxf(mx0, __shfl_xor_sync(0xFFFFFFFFu, mx0, 2));
        mx1 = fmaxf(mx1, __shfl_xor_sync(0xFFFFFFFFu, mx1, 1));
        mx1 = fmaxf(mx1, __shfl_xor_sync(0xFFFFFFFFu, mx1, 2));

        float nm0 = fmaxf(m0, mx0), nm1 = fmaxf(m1, mx1);
        float a0 = __expf(m0 - nm0), a1 = __expf(m1 - nm1);
        m0 = nm0; m1 = nm1;

        float s0 = 0.f, s1 = 0.f;
        unsigned pa[4][4];
        #pragma unroll
        for (int j = 0; j < 4; j++) {
            #pragma unroll
            for (int hv = 0; hv < 2; hv++) {
                int nt = 2 * j + hv;
                float p0 = __expf(sacc[nt][0] - m0);
                float p1 = __expf(sacc[nt][1] - m0);
                float p2 = __expf(sacc[nt][2] - m1);
                float p3 = __expf(sacc[nt][3] - m1);
                s0 += p0 + p1;
                s1 += p2 + p3;
                pa[j][hv * 2 + 0] = pack2(p0, p1);
                pa[j][hv * 2 + 1] = pack2(p2, p3);
            }
        }

        s0 += __shfl_xor_sync(0xFFFFFFFFu, s0, 1);
        s0 += __shfl_xor_sync(0xFFFFFFFFu, s0, 2);
        s1 += __shfl_xor_sync(0xFFFFFFFFu, s1, 1);
        s1 += __shfl_xor_sync(0xFFFFFFFFu, s1, 2);
        l0 = l0 * a0 + s0;
        l1 = l1 * a1 + s1;
        #pragma unroll
        for (int dt = 0; dt < 8; dt++) {
            oacc[dt][0] *= a0; oacc[dt][1] *= a0;
            oacc[dt][2] *= a1; oacc[dt][3] *= a1;
        }

        int mrow = lane & 7;
        int msel = lane >> 3;
        #pragma unroll
        for (int j = 0; j < 4; j++) {
            #pragma unroll
            for (int dp = 0; dp < 4; dp++) {
                int row = j * 16 + (msel & 1) * 8 + mrow;
                int col = dp * 16 + (msel >> 1) * 8;
                unsigned r[4];
                ldmx4t(r, &Vs[buf][row][col]);
                mma16(oacc[dp * 2 + 0], pa[j], r);
                mma16(oacc[dp * 2 + 1], pa[j], r + 2);
            }
        }
    }

    float inv0 = 1.0f / l0, inv1 = 1.0f / l1;
    int token = b * NTOK + qt * 64 + warp * 16 + g;
    __half* op = out + (size_t)token * DIMC + h * HDIM;
    #pragma unroll
    for (int dt = 0; dt < 8; dt++) {
        int d = dt * 8 + tg * 2;
        *(unsigned*)(op + d)            = pack2(oacc[dt][0] * inv0, oacc[dt][1] * inv0);
        *(unsigned*)(op + 8 * DIMC + d) = pack2(oacc[dt][2] * inv1, oacc[dt][3] * inv1);
    }
}

// ---------------------------------------------------------------------------
// kernel_launch
// ---------------------------------------------------------------------------
extern "C" void kernel_launch(void* const* d_in, const int* in_sizes, int n_in,
                              void* d_out, int out_size)
{
    const float* x      = (const float*)d_in[0];
    const float* w_qkv  = (const float*)d_in[1];
    const float* w_proj = (const float*)d_in[2];
    const float* b_proj = (const float*)d_in[3];
    float*       out    = (float*)d_out;

    void *qkv_p, *attn_p, *x_p, *wqkvT_p, *wprojT_p;
    cudaGetSymbolAddress(&qkv_p,   g_qkv);
    cudaGetSymbolAddress(&attn_p,  g_attn);
    cudaGetSymbolAddress(&x_p,     g_x);
    cudaGetSymbolAddress(&wqkvT_p, g_wqkvT);
    cudaGetSymbolAddress(&wprojT_p,g_wprojT);

    static bool attr_set = false;
    if (!attr_set) {
        cudaFuncSetAttribute((const void*)gemm_fp16<false, true>,
                             cudaFuncAttributeMaxDynamicSharedMemorySize, GEMM_SMEM);
        cudaFuncSetAttribute((const void*)gemm_fp16<true, false>,
                             cudaFuncAttributeMaxDynamicSharedMemorySize, GEMM_SMEM);
        attr_set = true;
    }

    // 0) prep
    {
        int n4x = MTOK * DIMC / 4;
        conv_half<<<(n4x + 255) / 256, 256>>>((const float4*)x, (__half*)x_p, n4x);
        transpose_half<<<dim3(3 * DIMC / 32, DIMC / 32), 256>>>(
            w_qkv, (__half*)wqkvT_p, DIMC, 3 * DIMC);
        transpose_half<<<dim3(DIMC / 32, DIMC / 32), 256>>>(
            w_proj, (__half*)wprojT_p, DIMC, DIMC);
    }

    // 1) QKV GEMM
    gemm_fp16<false, true><<<dim3(3 * DIMC / 128, MTOK / 128), 256, GEMM_SMEM>>>(
        (const __half*)x_p, (const __half*)wqkvT_p, nullptr, qkv_p,
        MTOK, 3 * DIMC, DIMC);

    // 2) Attention
    attn_fp16<<<dim3(NTOK / 64, NBATCH * NHEAD), 128>>>(
        (const __half*)qkv_p, (__half*)attn_p);

    // 3) Projection + bias
    gemm_fp16<true, false><<<dim3(DIMC / 128, MTOK / 128), 256, GEMM_SMEM>>>(
        (const __half*)attn_p, (const __half*)wprojT_p, b_proj, (void*)out,
        MTOK, DIMC, DIMC);
}